// round 14
// baseline (speedup 1.0000x reference)
#include <cuda_runtime.h>
#include <cstdint>

#define BB 2
#define TT 4096
#define CC 2048
#define NT (BB*TT)   // 8192 tokens

typedef unsigned long long ull;

// interleaved scan input: [tok][h][f][64], f: 0=r, 1=k, 2=wd, 3=v  (256MB)
__device__ float g_seq[(size_t)NT*32*4*64];

// ---------------- packed f32x2 helpers ----------------
__device__ __forceinline__ ull pk(float lo, float hi){
    ull r; asm("mov.b64 %0,{%1,%2};" : "=l"(r) : "f"(lo), "f"(hi)); return r;
}
__device__ __forceinline__ ull dup(float x){
    ull r; asm("mov.b64 %0,{%1,%1};" : "=l"(r) : "f"(x)); return r;
}
__device__ __forceinline__ float2 up2(ull a){
    float2 f; asm("mov.b64 {%0,%1},%2;" : "=f"(f.x), "=f"(f.y) : "l"(a)); return f;
}
__device__ __forceinline__ ull fma2(ull a, ull b, ull c){
    ull d; asm("fma.rn.f32x2 %0,%1,%2,%3;" : "=l"(d) : "l"(a), "l"(b), "l"(c)); return d;
}
__device__ __forceinline__ ull mul2(ull a, ull b){
    ull d; asm("mul.rn.f32x2 %0,%1,%2;" : "=l"(d) : "l"(a), "l"(b)); return d;
}
__device__ __forceinline__ void cpa16(uint32_t dst, const void* src){
    asm volatile("cp.async.cg.shared.global [%0],[%1],16;\n" :: "r"(dst), "l"(src) : "memory");
}
__device__ __forceinline__ void cpa_commit(){
    asm volatile("cp.async.commit_group;\n" ::: "memory");
}
__device__ __forceinline__ void cpa_wait0(){
    asm volatile("cp.async.wait_group 0;\n" ::: "memory");
}

// dummy kernel: shifts ncu launch parity so -s 5 -c 1 captures k_fused
__global__ void k_nop(){ }

// ---------------- k_fused shared layout (float offsets) ----------------
#define OFF_XXX 0            // [64][128]     8192
#define OFF_W2  8192         // [128][128]   16384  -> 24576
#define OFF_DW1 24576        // 2 x [128][68] 17408 -> 41984
#define OFF_XW  41984        // [64][132]     8448  -> 50432
#define OFF_A   50432        // [32][68]      2176  -> 52608
#define OFF_B   52608        // [32][128]     4096  -> 56704
// phase C reuse: D1 at 0 ([64][68] 4352), DW2 at 8192 ([64][128] 8192)
#define SMEM_F 56704
#define SMEM_BYTES (SMEM_F*4)

// =====================================================================
// k_fused: token-shift mix + decay LoRA. 64 tokens/block, 256 threads,
// grid 128. tx = tid&15 (8 output cols), ty = tid>>4 (4 tokens).
// (exact R5 version — measured ~586us)
// =====================================================================
__global__ __launch_bounds__(256, 1) void k_fused(
    const float* __restrict__ hidden, const float* __restrict__ attn_x,
    const float* __restrict__ maa_x,  const float* __restrict__ maa_w,
    const float* __restrict__ maa_k,  const float* __restrict__ maa_v,
    const float* __restrict__ maa_r,  const float* __restrict__ w1,
    const float* __restrict__ w2,     const float* __restrict__ dw1,
    const float* __restrict__ dw2,    const float* __restrict__ tdecay)
{
    extern __shared__ float sm[];
    const int tid = threadIdx.x;
    const int tx = tid & 15, ty = tid >> 4;
    const int bt0 = blockIdx.x * 64;

    const uint32_t smb = (uint32_t)__cvta_generic_to_shared(sm);

    // stage w2 + dw1 chunk via cp.async (one commit group)
    auto stage_wd = [&](int c0, int buf){
        #pragma unroll
        for (int l = 0; l < 16; l++){
            int i = tid + l*256;                // 0..4095 float4s
            int row = i >> 5, c4 = i & 31;
            cpa16(smb + (uint32_t)(OFF_W2 + row*128 + c4*4)*4u,
                  w2 + (size_t)row*CC + c0 + c4*4);
        }
        #pragma unroll
        for (int l = 0; l < 8; l++){
            int i = tid + l*256;                // 0..2047 float4s
            int row = i >> 4, c4 = i & 15;
            cpa16(smb + (uint32_t)(OFF_DW1 + buf*8704 + row*68 + c4*4)*4u,
                  dw1 + (size_t)(c0 + row)*64 + c4*4);
        }
        cpa_commit();
    };

    stage_wd(0, 0);

    // ================= Phase A: xxx = tanh(z @ W1[:,:128]) =================
    {
        float* As = sm + OFF_A;
        float* Bs = sm + OFF_B;
        float rx[8], rp[8], rm[8], rb[16];

        auto prefA = [&](int kc){
            #pragma unroll
            for (int l = 0; l < 8; l++){
                int i = tid + l*256; int kk = i & 31, tl = i >> 5;
                int tok = bt0 + tl; int c = kc + kk;
                rx[l] = hidden[(size_t)tok*CC + c];
                rp[l] = ((tok & (TT-1)) == 0) ? attn_x[(size_t)(tok >> 12)*CC + c]
                                              : hidden[(size_t)(tok-1)*CC + c];
                rm[l] = maa_x[c];
            }
            #pragma unroll
            for (int l = 0; l < 16; l++){
                int i = tid + l*256; int kk = i >> 7, n = i & 127;
                rb[l] = w1[(size_t)(kc+kk)*160 + n];
            }
        };

        ull acc[4][4];
        #pragma unroll
        for (int i = 0; i < 4; i++)
            #pragma unroll
            for (int j = 0; j < 4; j++) acc[i][j] = 0ull;

        prefA(0);
        for (int kc = 0; kc < CC; kc += 32){
            #pragma unroll
            for (int l = 0; l < 8; l++){
                int i = tid + l*256; int kk = i & 31, tl = i >> 5;
                As[kk*68 + tl] = rx[l] + (rp[l] - rx[l])*rm[l];
            }
            #pragma unroll
            for (int l = 0; l < 16; l++){
                int i = tid + l*256; int kk = i >> 7, n = i & 127;
                Bs[kk*128 + n] = rb[l];
            }
            __syncthreads();
            if (kc + 32 < CC) prefA(kc + 32);
            #pragma unroll
            for (int kk = 0; kk < 32; kk++){
                float4 av = *(const float4*)&As[kk*68 + ty*4];
                ulonglong2 b01 = *(const ulonglong2*)&Bs[kk*128 + tx*8];
                ulonglong2 b23 = *(const ulonglong2*)&Bs[kk*128 + tx*8 + 4];
                ull bp[4] = {b01.x, b01.y, b23.x, b23.y};
                float aa[4] = {av.x, av.y, av.z, av.w};
                #pragma unroll
                for (int i = 0; i < 4; i++){
                    ull ad = dup(aa[i]);
                    #pragma unroll
                    for (int j = 0; j < 4; j++) acc[i][j] = fma2(ad, bp[j], acc[i][j]);
                }
            }
            __syncthreads();
        }
        #pragma unroll
        for (int i = 0; i < 4; i++){
            #pragma unroll
            for (int jp = 0; jp < 4; jp++){
                float2 f = up2(acc[i][jp]);
                int r = (ty*4 + i)*128 + tx*8 + 2*jp;
                sm[OFF_XXX + r]   = tanhf(f.x);
                sm[OFF_XXX + r+1] = tanhf(f.y);
            }
        }
    }

    // ================= Phase B =================
    float* xxx_s = sm + OFF_XXX;
    float* w2_s  = sm + OFF_W2;
    float* xw_s  = sm + OFF_XW;

    ull acc_d1[4][2];
    #pragma unroll
    for (int i = 0; i < 4; i++){ acc_d1[i][0] = 0ull; acc_d1[i][1] = 0ull; }

    for (int c0 = 0; c0 < CC; c0 += 128){
        const int cbuf = (c0 >> 7) & 1;
        cpa_wait0();
        __syncthreads();           // w2/dw1 ready; also covers xxx after phase A

        const int cb = c0 + tx*8;
        const int hh = cb >> 6, lmm = cb & 63;

        // x / diff operands -> registers
        float xr[4][8], dr[4][8];
        #pragma unroll
        for (int i = 0; i < 4; i++){
            const int tok = bt0 + ty*4 + i;
            const size_t gofs = (size_t)tok*CC + cb;
            float4 xa = *(const float4*)&hidden[gofs];
            float4 xb = *(const float4*)&hidden[gofs + 4];
            const float* prow = ((tok & (TT-1)) == 0) ? (attn_x + (size_t)(tok >> 12)*CC)
                                                      : (hidden + (size_t)(tok-1)*CC);
            float4 pa = *(const float4*)&prow[cb];
            float4 pb = *(const float4*)&prow[cb + 4];
            xr[i][0]=xa.x; xr[i][1]=xa.y; xr[i][2]=xa.z; xr[i][3]=xa.w;
            xr[i][4]=xb.x; xr[i][5]=xb.y; xr[i][6]=xb.z; xr[i][7]=xb.w;
            dr[i][0]=pa.x-xa.x; dr[i][1]=pa.y-xa.y; dr[i][2]=pa.z-xa.z; dr[i][3]=pa.w-xa.w;
            dr[i][4]=pb.x-xb.x; dr[i][5]=pb.y-xb.y; dr[i][6]=pb.z-xb.z; dr[i][7]=pb.w-xb.w;
        }

        #pragma unroll
        for (int f = 0; f < 4; f++){
            ull macc[4][4];
            #pragma unroll
            for (int i = 0; i < 4; i++)
                #pragma unroll
                for (int j = 0; j < 4; j++) macc[i][j] = 0ull;

            #pragma unroll
            for (int kk = 0; kk < 32; kk++){
                ulonglong2 wa = *(const ulonglong2*)&w2_s[(f*32+kk)*128 + tx*8];
                ulonglong2 wb = *(const ulonglong2*)&w2_s[(f*32+kk)*128 + tx*8 + 4];
                ull bp[4] = {wa.x, wa.y, wb.x, wb.y};
                #pragma unroll
                for (int i = 0; i < 4; i++){
                    ull ad = dup(xxx_s[(ty*4 + i)*128 + f*32 + kk]);
                    #pragma unroll
                    for (int j = 0; j < 4; j++) macc[i][j] = fma2(ad, bp[j], macc[i][j]);
                }
            }
            const float* maaf = (f==0) ? maa_w : (f==1) ? maa_k : (f==2) ? maa_v : maa_r;
            float4 ma = *(const float4*)&maaf[cb];
            float4 mb = *(const float4*)&maaf[cb + 4];
            float mmv[8] = {ma.x,ma.y,ma.z,ma.w,mb.x,mb.y,mb.z,mb.w};
            const int slot = (f==1) ? 1 : (f==2) ? 3 : 0;
            #pragma unroll
            for (int i = 0; i < 4; i++){
                const int tl = ty*4 + i;
                float mq[8];
                #pragma unroll
                for (int jp = 0; jp < 4; jp++){
                    float2 q = up2(macc[i][jp]);
                    mq[2*jp] = q.x; mq[2*jp+1] = q.y;
                }
                float o[8];
                #pragma unroll
                for (int e = 0; e < 8; e++) o[e] = xr[i][e] + dr[i][e]*(mmv[e] + mq[e]);
                if (f == 0){
                    *(float4*)&xw_s[tl*132 + tx*8]     = make_float4(o[0],o[1],o[2],o[3]);
                    *(float4*)&xw_s[tl*132 + tx*8 + 4] = make_float4(o[4],o[5],o[6],o[7]);
                } else {
                    float* dst = &g_seq[((size_t)(bt0 + tl)*32 + hh)*256 + slot*64 + lmm];
                    *(float4*)&dst[0] = make_float4(o[0],o[1],o[2],o[3]);
                    *(float4*)&dst[4] = make_float4(o[4],o[5],o[6],o[7]);
                }
            }
        }
        __syncthreads();           // xw_s complete; w2/dw1 fully consumed

        if (c0 + 128 < CC) stage_wd(c0 + 128, cbuf ^ 1);
        else               cpa_commit();

        const float* dw1c = sm + OFF_DW1 + cbuf*8704;
        #pragma unroll 2
        for (int kk = 0; kk < 128; kk++){
            ulonglong2 bp = *(const ulonglong2*)&dw1c[kk*68 + tx*4];
            #pragma unroll
            for (int i = 0; i < 4; i++){
                ull ad = dup(xw_s[(ty*4 + i)*132 + kk]);
                acc_d1[i][0] = fma2(ad, bp.x, acc_d1[i][0]);
                acc_d1[i][1] = fma2(ad, bp.y, acc_d1[i][1]);
            }
        }
    }
    cpa_wait0();
    __syncthreads();

    // ================= Phase C: wd = exp(-exp(td + tanh(d1) @ dw2)) =================
    float* d1_s  = sm;             // [64][68]
    float* dw2_s = sm + 8192;      // [64][128]
    #pragma unroll
    for (int i = 0; i < 4; i++){
        float2 e0 = up2(acc_d1[i][0]);
        float2 e1 = up2(acc_d1[i][1]);
        int r = (ty*4 + i)*68 + tx*4;
        d1_s[r]   = tanhf(e0.x);
        d1_s[r+1] = tanhf(e0.y);
        d1_s[r+2] = tanhf(e1.x);
        d1_s[r+3] = tanhf(e1.y);
    }
    __syncthreads();

    for (int c0 = 0; c0 < CC; c0 += 128){
        #pragma unroll
        for (int l = 0; l < 32; l++){
            int i = tid + l*256;
            dw2_s[i] = dw2[(size_t)(i >> 7)*CC + c0 + (i & 127)];
        }
        __syncthreads();
        ull wacc[4][4];
        #pragma unroll
        for (int i = 0; i < 4; i++)
            #pragma unroll
            for (int j = 0; j < 4; j++) wacc[i][j] = 0ull;
        #pragma unroll 4
        for (int jj = 0; jj < 64; jj++){
            ulonglong2 wa = *(const ulonglong2*)&dw2_s[jj*128 + tx*8];
            ulonglong2 wb = *(const ulonglong2*)&dw2_s[jj*128 + tx*8 + 4];
            #pragma unroll
            for (int i = 0; i < 4; i++){
                ull ad = dup(d1_s[(ty*4 + i)*68 + jj]);
                wacc[i][0] = fma2(ad, wa.x, wacc[i][0]);
                wacc[i][1] = fma2(ad, wa.y, wacc[i][1]);
                wacc[i][2] = fma2(ad, wb.x, wacc[i][2]);
                wacc[i][3] = fma2(ad, wb.y, wacc[i][3]);
            }
        }
        const int cb = c0 + tx*8;
        const int hh = cb >> 6, lmm = cb & 63;
        float4 t0 = *(const float4*)&tdecay[cb];
        float4 t1 = *(const float4*)&tdecay[cb + 4];
        float td[8] = {t0.x,t0.y,t0.z,t0.w,t1.x,t1.y,t1.z,t1.w};
        #pragma unroll
        for (int i = 0; i < 4; i++){
            const int tl = ty*4 + i;
            float mq[8];
            #pragma unroll
            for (int jp = 0; jp < 4; jp++){
                float2 q = up2(wacc[i][jp]);
                mq[2*jp] = q.x; mq[2*jp+1] = q.y;
            }
            float o[8];
            #pragma unroll
            for (int e = 0; e < 8; e++) o[e] = expf(-expf(td[e] + mq[e]));
            float* dst = &g_seq[((size_t)(bt0 + tl)*32 + hh)*256 + 128 + lmm];
            *(float4*)&dst[0] = make_float4(o[0],o[1],o[2],o[3]);
            *(float4*)&dst[4] = make_float4(o[4],o[5],o[6],o[7]);
        }
        __syncthreads();
    }
}

// =====================================================================
// k_scan: exact R4 version (measured 365us). 128 blocks = (b, h, m-half).
// 256 threads: lm = tid&31, q = tid>>5 (8 n-octets). 4 f32x2 state
// pairs/thread. cp.async ring: 32 steps (4 groups of 8).
// =====================================================================
__global__ __launch_bounds__(256) void k_scan(
    const float* __restrict__ attn_kv, const float* __restrict__ faaaa,
    float* __restrict__ out)
{
    __shared__ float ring[32*256];
    __shared__ float partial[8][264];

    const int tid = threadIdx.x;
    const int bid = blockIdx.x;
    const int b = bid >> 6, h = (bid >> 1) & 31, half = bid & 1;
    const int lm = tid & 31, q = tid >> 5;
    const int mg = half*32 + lm;

    const ull ud = dup(faaaa[h]);

    ull s2[4];
    const float* kvp = attn_kv + ((size_t)(b*32 + h))*4096;
    #pragma unroll
    for (int j = 0; j < 4; j++){
        int n0 = q*8 + 2*j;
        s2[j] = pk(kvp[n0*64 + mg], kvp[(n0+1)*64 + mg]);
    }

    const float4* srcb = (const float4*)g_seq + ((size_t)b*TT)*2048 + h*64;
    const uint32_t rbase = (uint32_t)__cvta_generic_to_shared(ring);
    const int e0 = tid*2, e1 = tid*2 + 1;
    const int s0 = e0 >> 6, o0 = e0 & 63;
    const int s1 = e1 >> 6, o1 = e1 & 63;

    #pragma unroll
    for (int gg = 0; gg < 3; gg++){
        int t0 = gg*8;
        int ta = t0 + s0, tb = t0 + s1;
        cpa16(rbase + (uint32_t)((ta & 31)*1024 + o0*16), srcb + (size_t)ta*2048 + o0);
        cpa16(rbase + (uint32_t)((tb & 31)*1024 + o1*16), srcb + (size_t)tb*2048 + o1);
        cpa_commit();
    }

    const size_t obase = (size_t)b*TT*CC + h*64 + half*32;
    const int nb = q*8;

    for (int g = 0; g < TT/8; g++){
        asm volatile("cp.async.wait_group 2;\n" ::: "memory");
        __syncthreads();
        #pragma unroll
        for (int ti = 0; ti < 8; ti++){
            const float* st = &ring[(((g << 3) + ti) & 31) << 8];
            const ull vd = dup(st[192 + mg]);
            ulonglong2 ra = *(const ulonglong2*)&st[nb];
            ulonglong2 rb = *(const ulonglong2*)&st[nb + 4];
            ulonglong2 ka = *(const ulonglong2*)&st[64 + nb];
            ulonglong2 kb = *(const ulonglong2*)&st[64 + nb + 4];
            ulonglong2 wa = *(const ulonglong2*)&st[128 + nb];
            ulonglong2 wb = *(const ulonglong2*)&st[128 + nb + 4];
            ull r2[4]  = {ra.x, ra.y, rb.x, rb.y};
            ull k2[4]  = {ka.x, ka.y, kb.x, kb.y};
            ull w2v[4] = {wa.x, wa.y, wb.x, wb.y};
            ull y0 = 0ull, y1 = 0ull;
            #pragma unroll
            for (int j = 0; j < 4; j++){
                ull a2 = mul2(k2[j], vd);
                ull t2 = fma2(ud, a2, s2[j]);
                if (j & 1) y1 = fma2(r2[j], t2, y1);
                else       y0 = fma2(r2[j], t2, y0);
                s2[j] = fma2(w2v[j], s2[j], a2);
            }
            float2 f0 = up2(y0), f1 = up2(y1);
            partial[ti][q*33 + lm] = (f0.x + f0.y) + (f1.x + f1.y);
        }
        __syncthreads();
        {
            const int s = tid >> 5;
            float y = 0.f;
            #pragma unroll
            for (int q2 = 0; q2 < 8; q2++) y += partial[s][q2*33 + lm];
            out[obase + (size_t)((g << 3) + s)*CC + lm] = y;
        }
        if (g + 3 < TT/8){
            int t0 = (g + 3)*8;
            int ta = t0 + s0, tb = t0 + s1;
            cpa16(rbase + (uint32_t)((ta & 31)*1024 + o0*16), srcb + (size_t)ta*2048 + o0);
            cpa16(rbase + (uint32_t)((tb & 31)*1024 + o1*16), srcb + (size_t)tb*2048 + o1);
        }
        cpa_commit();
    }
}

// =====================================================================
extern "C" void kernel_launch(void* const* d_in, const int* in_sizes, int n_in,
                              void* d_out, int out_size) {
    const float* hidden  = (const float*)d_in[0];
    const float* attn_x  = (const float*)d_in[1];
    const float* attn_kv = (const float*)d_in[2];
    const float* maa_x   = (const float*)d_in[4];
    const float* maa_w   = (const float*)d_in[5];
    const float* maa_k   = (const float*)d_in[6];
    const float* maa_v   = (const float*)d_in[7];
    const float* maa_r   = (const float*)d_in[8];
    const float* w1      = (const float*)d_in[10];
    const float* w2      = (const float*)d_in[11];
    const float* tdecay  = (const float*)d_in[12];
    const float* dw1     = (const float*)d_in[13];
    const float* dw2     = (const float*)d_in[14];
    const float* faaaa   = (const float*)d_in[15];
    float* out = (float*)d_out;

    static bool attr_set = false;
    if (!attr_set){
        cudaFuncSetAttribute(k_fused, cudaFuncAttributeMaxDynamicSharedMemorySize, SMEM_BYTES);
        attr_set = true;
    }

    // launch order [nop, fused, scan, nop]: 6th global launch = k_fused,
    // so ncu (-s 5 -c 1) finally profiles the dominant kernel.
    k_nop<<<1, 32>>>();
    k_fused<<<NT/64, 256, SMEM_BYTES>>>(hidden, attn_x, maa_x, maa_w, maa_k,
                                        maa_v, maa_r, w1, w2, dw1, dw2, tdecay);
    k_scan <<<128, 256>>>(attn_kv, faaaa, out);
    k_nop<<<1, 32>>>();
}

// round 15
// speedup vs baseline: 1.8492x; 1.8492x over previous
#include <cuda_runtime.h>
#include <cstdint>

#define BB 2
#define TT 4096
#define CC 2048
#define NT (BB*TT)   // 8192 tokens

typedef unsigned long long ull;

// interleaved scan input: [tok][h][f][64], f: 0=r, 1=k, 2=wd, 3=v  (256MB)
__device__ float g_seq[(size_t)NT*32*4*64];

// ---------------- packed f32x2 helpers ----------------
__device__ __forceinline__ ull pk(float lo, float hi){
    ull r; asm("mov.b64 %0,{%1,%2};" : "=l"(r) : "f"(lo), "f"(hi)); return r;
}
__device__ __forceinline__ ull dup(float x){
    ull r; asm("mov.b64 %0,{%1,%1};" : "=l"(r) : "f"(x)); return r;
}
__device__ __forceinline__ float2 up2(ull a){
    float2 f; asm("mov.b64 {%0,%1},%2;" : "=f"(f.x), "=f"(f.y) : "l"(a)); return f;
}
__device__ __forceinline__ ull fma2(ull a, ull b, ull c){
    ull d; asm("fma.rn.f32x2 %0,%1,%2,%3;" : "=l"(d) : "l"(a), "l"(b), "l"(c)); return d;
}
__device__ __forceinline__ ull mul2(ull a, ull b){
    ull d; asm("mul.rn.f32x2 %0,%1,%2;" : "=l"(d) : "l"(a), "l"(b)); return d;
}
__device__ __forceinline__ void cpa16(uint32_t dst, const void* src){
    asm volatile("cp.async.cg.shared.global [%0],[%1],16;\n" :: "r"(dst), "l"(src) : "memory");
}
__device__ __forceinline__ void cpa_commit(){
    asm volatile("cp.async.commit_group;\n" ::: "memory");
}
__device__ __forceinline__ void cpa_wait0(){
    asm volatile("cp.async.wait_group 0;\n" ::: "memory");
}
__device__ __forceinline__ uint32_t tf32r(float f){
    uint32_t u; asm("cvt.rna.tf32.f32 %0, %1;" : "=r"(u) : "f"(f)); return u;
}
__device__ __forceinline__ void mma_tf32(float* c, uint32_t a0, uint32_t a1,
                                         uint32_t a2, uint32_t a3,
                                         uint32_t b0, uint32_t b1){
    asm("mma.sync.aligned.m16n8k8.row.col.f32.tf32.tf32.f32 "
        "{%0,%1,%2,%3}, {%4,%5,%6,%7}, {%8,%9}, {%0,%1,%2,%3};"
        : "+f"(c[0]), "+f"(c[1]), "+f"(c[2]), "+f"(c[3])
        : "r"(a0), "r"(a1), "r"(a2), "r"(a3), "r"(b0), "r"(b1));
}

// ---------------- k_fused shared layout (float offsets) ----------------
#define OFF_XXX 0            // [64][128]     8192
#define OFF_W2  8192         // [128][128]   16384  -> 24576
#define OFF_DW1 24576        // 2 x [128][68] 17408 -> 41984
#define OFF_XW  41984        // [64][132]     8448  -> 50432
#define OFF_A   50432        // [32][72]      2304  -> 52736  (phase A, tf32 bits)
#define OFF_BT  52736        // [128][36]     4608  -> 57344  (phase A, tf32 bits)
// phase C reuse: D1 at 0 ([64][68] 4352), DW2 at 8192 ([64][128] 8192)
#define SMEM_F 57344
#define SMEM_BYTES (SMEM_F*4)

// =====================================================================
// k_fused: token-shift mix + decay LoRA. 64 tokens/block, 256 threads,
// grid 128. Phase A uses tf32 mma.sync; Phases B/C identical to the
// measured-586us R5 version.
// =====================================================================
__global__ __launch_bounds__(256, 1) void k_fused(
    const float* __restrict__ hidden, const float* __restrict__ attn_x,
    const float* __restrict__ maa_x,  const float* __restrict__ maa_w,
    const float* __restrict__ maa_k,  const float* __restrict__ maa_v,
    const float* __restrict__ maa_r,  const float* __restrict__ w1,
    const float* __restrict__ w2,     const float* __restrict__ dw1,
    const float* __restrict__ dw2,    const float* __restrict__ tdecay)
{
    extern __shared__ float sm[];
    const int tid = threadIdx.x;
    const int tx = tid & 15, ty = tid >> 4;
    const int bt0 = blockIdx.x * 64;

    const uint32_t smb = (uint32_t)__cvta_generic_to_shared(sm);

    // stage w2 + dw1 chunk via cp.async (one commit group)
    auto stage_wd = [&](int c0, int buf){
        #pragma unroll
        for (int l = 0; l < 16; l++){
            int i = tid + l*256;                // 0..4095 float4s
            int row = i >> 5, c4 = i & 31;
            cpa16(smb + (uint32_t)(OFF_W2 + row*128 + c4*4)*4u,
                  w2 + (size_t)row*CC + c0 + c4*4);
        }
        #pragma unroll
        for (int l = 0; l < 8; l++){
            int i = tid + l*256;                // 0..2047 float4s
            int row = i >> 4, c4 = i & 15;
            cpa16(smb + (uint32_t)(OFF_DW1 + buf*8704 + row*68 + c4*4)*4u,
                  dw1 + (size_t)(c0 + row)*64 + c4*4);
        }
        cpa_commit();
    };

    stage_wd(0, 0);

    // ========== Phase A: xxx = tanh(z @ W1[:,:128]) via tf32 mma ==========
    {
        float* As  = sm + OFF_A;    // [32][72] tf32 bits (k-major)
        float* Bst = sm + OFF_BT;   // [128][36] tf32 bits (n-major)
        float rx[8], rp[8], rm[8], rb[16];

        auto prefA = [&](int kc){
            #pragma unroll
            for (int l = 0; l < 8; l++){
                int i = tid + l*256; int kk = i & 31, tl = i >> 5;
                int tok = bt0 + tl; int c = kc + kk;
                rx[l] = hidden[(size_t)tok*CC + c];
                rp[l] = ((tok & (TT-1)) == 0) ? attn_x[(size_t)(tok >> 12)*CC + c]
                                              : hidden[(size_t)(tok-1)*CC + c];
                rm[l] = maa_x[c];
            }
            #pragma unroll
            for (int l = 0; l < 16; l++){
                int i = tid + l*256; int kk = i >> 7, n = i & 127;
                rb[l] = w1[(size_t)(kc+kk)*160 + n];
            }
        };

        const int wid  = tid >> 5, lane = tid & 31;
        const int gid  = lane >> 2, tig = lane & 3;
        const int tokb = (wid & 3) * 16;      // token tile base (0..48)
        const int nh   = wid >> 2;            // n half (0..1)

        float cA[8][4];
        #pragma unroll
        for (int ns = 0; ns < 8; ns++)
            #pragma unroll
            for (int j = 0; j < 4; j++) cA[ns][j] = 0.f;

        prefA(0);
        for (int kc = 0; kc < CC; kc += 32){
            #pragma unroll
            for (int l = 0; l < 8; l++){
                int i = tid + l*256; int kk = i & 31, tl = i >> 5;
                float z = rx[l] + (rp[l] - rx[l])*rm[l];
                As[kk*72 + tl] = __uint_as_float(tf32r(z));
            }
            #pragma unroll
            for (int l = 0; l < 16; l++){
                int i = tid + l*256; int kk = i >> 7, n = i & 127;
                Bst[n*36 + kk] = __uint_as_float(tf32r(rb[l]));
            }
            __syncthreads();
            if (kc + 32 < CC) prefA(kc + 32);
            #pragma unroll
            for (int ks = 0; ks < 4; ks++){
                const int k0 = ks*8;
                uint32_t a0 = __float_as_uint(As[(k0+tig  )*72 + tokb + gid    ]);
                uint32_t a1 = __float_as_uint(As[(k0+tig  )*72 + tokb + gid + 8]);
                uint32_t a2 = __float_as_uint(As[(k0+tig+4)*72 + tokb + gid    ]);
                uint32_t a3 = __float_as_uint(As[(k0+tig+4)*72 + tokb + gid + 8]);
                #pragma unroll
                for (int ns = 0; ns < 8; ns++){
                    const int n0 = nh*64 + ns*8;
                    uint32_t b0 = __float_as_uint(Bst[(n0+gid)*36 + k0 + tig    ]);
                    uint32_t b1 = __float_as_uint(Bst[(n0+gid)*36 + k0 + tig + 4]);
                    mma_tf32(cA[ns], a0, a1, a2, a3, b0, b1);
                }
            }
            __syncthreads();
        }
        // epilogue: tanh -> xxx_s[tok*128 + n]
        #pragma unroll
        for (int ns = 0; ns < 8; ns++){
            const int n0 = nh*64 + ns*8 + 2*tig;
            const int t0 = tokb + gid;
            sm[OFF_XXX + (t0    )*128 + n0    ] = tanhf(cA[ns][0]);
            sm[OFF_XXX + (t0    )*128 + n0 + 1] = tanhf(cA[ns][1]);
            sm[OFF_XXX + (t0 + 8)*128 + n0    ] = tanhf(cA[ns][2]);
            sm[OFF_XXX + (t0 + 8)*128 + n0 + 1] = tanhf(cA[ns][3]);
        }
    }

    // ================= Phase B =================
    float* xxx_s = sm + OFF_XXX;
    float* w2_s  = sm + OFF_W2;
    float* xw_s  = sm + OFF_XW;

    ull acc_d1[4][2];
    #pragma unroll
    for (int i = 0; i < 4; i++){ acc_d1[i][0] = 0ull; acc_d1[i][1] = 0ull; }

    for (int c0 = 0; c0 < CC; c0 += 128){
        const int cbuf = (c0 >> 7) & 1;
        cpa_wait0();
        __syncthreads();           // w2/dw1 ready; also covers xxx after phase A

        const int cb = c0 + tx*8;
        const int hh = cb >> 6, lmm = cb & 63;

        // x / diff operands -> registers
        float xr[4][8], dr[4][8];
        #pragma unroll
        for (int i = 0; i < 4; i++){
            const int tok = bt0 + ty*4 + i;
            const size_t gofs = (size_t)tok*CC + cb;
            float4 xa = *(const float4*)&hidden[gofs];
            float4 xb = *(const float4*)&hidden[gofs + 4];
            const float* prow = ((tok & (TT-1)) == 0) ? (attn_x + (size_t)(tok >> 12)*CC)
                                                      : (hidden + (size_t)(tok-1)*CC);
            float4 pa = *(const float4*)&prow[cb];
            float4 pb = *(const float4*)&prow[cb + 4];
            xr[i][0]=xa.x; xr[i][1]=xa.y; xr[i][2]=xa.z; xr[i][3]=xa.w;
            xr[i][4]=xb.x; xr[i][5]=xb.y; xr[i][6]=xb.z; xr[i][7]=xb.w;
            dr[i][0]=pa.x-xa.x; dr[i][1]=pa.y-xa.y; dr[i][2]=pa.z-xa.z; dr[i][3]=pa.w-xa.w;
            dr[i][4]=pb.x-xb.x; dr[i][5]=pb.y-xb.y; dr[i][6]=pb.z-xb.z; dr[i][7]=pb.w-xb.w;
        }

        #pragma unroll
        for (int f = 0; f < 4; f++){
            ull macc[4][4];
            #pragma unroll
            for (int i = 0; i < 4; i++)
                #pragma unroll
                for (int j = 0; j < 4; j++) macc[i][j] = 0ull;

            #pragma unroll
            for (int kk = 0; kk < 32; kk++){
                ulonglong2 wa = *(const ulonglong2*)&w2_s[(f*32+kk)*128 + tx*8];
                ulonglong2 wb = *(const ulonglong2*)&w2_s[(f*32+kk)*128 + tx*8 + 4];
                ull bp[4] = {wa.x, wa.y, wb.x, wb.y};
                #pragma unroll
                for (int i = 0; i < 4; i++){
                    ull ad = dup(xxx_s[(ty*4 + i)*128 + f*32 + kk]);
                    #pragma unroll
                    for (int j = 0; j < 4; j++) macc[i][j] = fma2(ad, bp[j], macc[i][j]);
                }
            }
            const float* maaf = (f==0) ? maa_w : (f==1) ? maa_k : (f==2) ? maa_v : maa_r;
            float4 ma = *(const float4*)&maaf[cb];
            float4 mb = *(const float4*)&maaf[cb + 4];
            float mmv[8] = {ma.x,ma.y,ma.z,ma.w,mb.x,mb.y,mb.z,mb.w};
            const int slot = (f==1) ? 1 : (f==2) ? 3 : 0;
            #pragma unroll
            for (int i = 0; i < 4; i++){
                const int tl = ty*4 + i;
                float mq[8];
                #pragma unroll
                for (int jp = 0; jp < 4; jp++){
                    float2 q = up2(macc[i][jp]);
                    mq[2*jp] = q.x; mq[2*jp+1] = q.y;
                }
                float o[8];
                #pragma unroll
                for (int e = 0; e < 8; e++) o[e] = xr[i][e] + dr[i][e]*(mmv[e] + mq[e]);
                if (f == 0){
                    *(float4*)&xw_s[tl*132 + tx*8]     = make_float4(o[0],o[1],o[2],o[3]);
                    *(float4*)&xw_s[tl*132 + tx*8 + 4] = make_float4(o[4],o[5],o[6],o[7]);
                } else {
                    float* dst = &g_seq[((size_t)(bt0 + tl)*32 + hh)*256 + slot*64 + lmm];
                    *(float4*)&dst[0] = make_float4(o[0],o[1],o[2],o[3]);
                    *(float4*)&dst[4] = make_float4(o[4],o[5],o[6],o[7]);
                }
            }
        }
        __syncthreads();           // xw_s complete; w2/dw1 fully consumed

        if (c0 + 128 < CC) stage_wd(c0 + 128, cbuf ^ 1);
        else               cpa_commit();

        const float* dw1c = sm + OFF_DW1 + cbuf*8704;
        #pragma unroll 2
        for (int kk = 0; kk < 128; kk++){
            ulonglong2 bp = *(const ulonglong2*)&dw1c[kk*68 + tx*4];
            #pragma unroll
            for (int i = 0; i < 4; i++){
                ull ad = dup(xw_s[(ty*4 + i)*132 + kk]);
                acc_d1[i][0] = fma2(ad, bp.x, acc_d1[i][0]);
                acc_d1[i][1] = fma2(ad, bp.y, acc_d1[i][1]);
            }
        }
    }
    cpa_wait0();
    __syncthreads();

    // ================= Phase C: wd = exp(-exp(td + tanh(d1) @ dw2)) =================
    float* d1_s  = sm;             // [64][68]
    float* dw2_s = sm + 8192;      // [64][128]
    #pragma unroll
    for (int i = 0; i < 4; i++){
        float2 e0 = up2(acc_d1[i][0]);
        float2 e1 = up2(acc_d1[i][1]);
        int r = (ty*4 + i)*68 + tx*4;
        d1_s[r]   = tanhf(e0.x);
        d1_s[r+1] = tanhf(e0.y);
        d1_s[r+2] = tanhf(e1.x);
        d1_s[r+3] = tanhf(e1.y);
    }
    __syncthreads();

    for (int c0 = 0; c0 < CC; c0 += 128){
        #pragma unroll
        for (int l = 0; l < 32; l++){
            int i = tid + l*256;
            dw2_s[i] = dw2[(size_t)(i >> 7)*CC + c0 + (i & 127)];
        }
        __syncthreads();
        ull wacc[4][4];
        #pragma unroll
        for (int i = 0; i < 4; i++)
            #pragma unroll
            for (int j = 0; j < 4; j++) wacc[i][j] = 0ull;
        #pragma unroll 4
        for (int jj = 0; jj < 64; jj++){
            ulonglong2 wa = *(const ulonglong2*)&dw2_s[jj*128 + tx*8];
            ulonglong2 wb = *(const ulonglong2*)&dw2_s[jj*128 + tx*8 + 4];
            #pragma unroll
            for (int i = 0; i < 4; i++){
                ull ad = dup(d1_s[(ty*4 + i)*68 + jj]);
                wacc[i][0] = fma2(ad, wa.x, wacc[i][0]);
                wacc[i][1] = fma2(ad, wa.y, wacc[i][1]);
                wacc[i][2] = fma2(ad, wb.x, wacc[i][2]);
                wacc[i][3] = fma2(ad, wb.y, wacc[i][3]);
            }
        }
        const int cb = c0 + tx*8;
        const int hh = cb >> 6, lmm = cb & 63;
        float4 t0 = *(const float4*)&tdecay[cb];
        float4 t1 = *(const float4*)&tdecay[cb + 4];
        float td[8] = {t0.x,t0.y,t0.z,t0.w,t1.x,t1.y,t1.z,t1.w};
        #pragma unroll
        for (int i = 0; i < 4; i++){
            const int tl = ty*4 + i;
            float mq[8];
            #pragma unroll
            for (int jp = 0; jp < 4; jp++){
                float2 q = up2(wacc[i][jp]);
                mq[2*jp] = q.x; mq[2*jp+1] = q.y;
            }
            float o[8];
            #pragma unroll
            for (int e = 0; e < 8; e++) o[e] = expf(-expf(td[e] + mq[e]));
            float* dst = &g_seq[((size_t)(bt0 + tl)*32 + hh)*256 + 128 + lmm];
            *(float4*)&dst[0] = make_float4(o[0],o[1],o[2],o[3]);
            *(float4*)&dst[4] = make_float4(o[4],o[5],o[6],o[7]);
        }
        __syncthreads();
    }
}

// =====================================================================
// k_scan: exact R4 version (measured 365us). 128 blocks = (b, h, m-half).
// 256 threads: lm = tid&31, q = tid>>5 (8 n-octets). 4 f32x2 state
// pairs/thread. cp.async ring: 32 steps (4 groups of 8).
// =====================================================================
__global__ __launch_bounds__(256) void k_scan(
    const float* __restrict__ attn_kv, const float* __restrict__ faaaa,
    float* __restrict__ out)
{
    __shared__ float ring[32*256];
    __shared__ float partial[8][264];

    const int tid = threadIdx.x;
    const int bid = blockIdx.x;
    const int b = bid >> 6, h = (bid >> 1) & 31, half = bid & 1;
    const int lm = tid & 31, q = tid >> 5;
    const int mg = half*32 + lm;

    const ull ud = dup(faaaa[h]);

    ull s2[4];
    const float* kvp = attn_kv + ((size_t)(b*32 + h))*4096;
    #pragma unroll
    for (int j = 0; j < 4; j++){
        int n0 = q*8 + 2*j;
        s2[j] = pk(kvp[n0*64 + mg], kvp[(n0+1)*64 + mg]);
    }

    const float4* srcb = (const float4*)g_seq + ((size_t)b*TT)*2048 + h*64;
    const uint32_t rbase = (uint32_t)__cvta_generic_to_shared(ring);
    const int e0 = tid*2, e1 = tid*2 + 1;
    const int s0 = e0 >> 6, o0 = e0 & 63;
    const int s1 = e1 >> 6, o1 = e1 & 63;

    #pragma unroll
    for (int gg = 0; gg < 3; gg++){
        int t0 = gg*8;
        int ta = t0 + s0, tb = t0 + s1;
        cpa16(rbase + (uint32_t)((ta & 31)*1024 + o0*16), srcb + (size_t)ta*2048 + o0);
        cpa16(rbase + (uint32_t)((tb & 31)*1024 + o1*16), srcb + (size_t)tb*2048 + o1);
        cpa_commit();
    }

    const size_t obase = (size_t)b*TT*CC + h*64 + half*32;
    const int nb = q*8;

    for (int g = 0; g < TT/8; g++){
        asm volatile("cp.async.wait_group 2;\n" ::: "memory");
        __syncthreads();
        #pragma unroll
        for (int ti = 0; ti < 8; ti++){
            const float* st = &ring[(((g << 3) + ti) & 31) << 8];
            const ull vd = dup(st[192 + mg]);
            ulonglong2 ra = *(const ulonglong2*)&st[nb];
            ulonglong2 rb = *(const ulonglong2*)&st[nb + 4];
            ulonglong2 ka = *(const ulonglong2*)&st[64 + nb];
            ulonglong2 kb = *(const ulonglong2*)&st[64 + nb + 4];
            ulonglong2 wa = *(const ulonglong2*)&st[128 + nb];
            ulonglong2 wb = *(const ulonglong2*)&st[128 + nb + 4];
            ull r2[4]  = {ra.x, ra.y, rb.x, rb.y};
            ull k2[4]  = {ka.x, ka.y, kb.x, kb.y};
            ull w2v[4] = {wa.x, wa.y, wb.x, wb.y};
            ull y0 = 0ull, y1 = 0ull;
            #pragma unroll
            for (int j = 0; j < 4; j++){
                ull a2 = mul2(k2[j], vd);
                ull t2 = fma2(ud, a2, s2[j]);
                if (j & 1) y1 = fma2(r2[j], t2, y1);
                else       y0 = fma2(r2[j], t2, y0);
                s2[j] = fma2(w2v[j], s2[j], a2);
            }
            float2 f0 = up2(y0), f1 = up2(y1);
            partial[ti][q*33 + lm] = (f0.x + f0.y) + (f1.x + f1.y);
        }
        __syncthreads();
        {
            const int s = tid >> 5;
            float y = 0.f;
            #pragma unroll
            for (int q2 = 0; q2 < 8; q2++) y += partial[s][q2*33 + lm];
            out[obase + (size_t)((g << 3) + s)*CC + lm] = y;
        }
        if (g + 3 < TT/8){
            int t0 = (g + 3)*8;
            int ta = t0 + s0, tb = t0 + s1;
            cpa16(rbase + (uint32_t)((ta & 31)*1024 + o0*16), srcb + (size_t)ta*2048 + o0);
            cpa16(rbase + (uint32_t)((tb & 31)*1024 + o1*16), srcb + (size_t)tb*2048 + o1);
        }
        cpa_commit();
    }
}

// =====================================================================
extern "C" void kernel_launch(void* const* d_in, const int* in_sizes, int n_in,
                              void* d_out, int out_size) {
    const float* hidden  = (const float*)d_in[0];
    const float* attn_x  = (const float*)d_in[1];
    const float* attn_kv = (const float*)d_in[2];
    const float* maa_x   = (const float*)d_in[4];
    const float* maa_w   = (const float*)d_in[5];
    const float* maa_k   = (const float*)d_in[6];
    const float* maa_v   = (const float*)d_in[7];
    const float* maa_r   = (const float*)d_in[8];
    const float* w1      = (const float*)d_in[10];
    const float* w2      = (const float*)d_in[11];
    const float* tdecay  = (const float*)d_in[12];
    const float* dw1     = (const float*)d_in[13];
    const float* dw2     = (const float*)d_in[14];
    const float* faaaa   = (const float*)d_in[15];
    float* out = (float*)d_out;

    static bool attr_set = false;
    if (!attr_set){
        cudaFuncSetAttribute(k_fused, cudaFuncAttributeMaxDynamicSharedMemorySize, SMEM_BYTES);
        attr_set = true;
    }

    k_fused<<<NT/64, 256, SMEM_BYTES>>>(hidden, attn_x, maa_x, maa_w, maa_k,
                                        maa_v, maa_r, w1, w2, dw1, dw2, tdecay);
    k_scan <<<128, 256>>>(attn_kv, faaaa, out);
}

// round 16
// speedup vs baseline: 2.0675x; 1.1180x over previous
#include <cuda_runtime.h>
#include <cstdint>

#define BB 2
#define TT 4096
#define CC 2048
#define NT (BB*TT)   // 8192 tokens

typedef unsigned long long ull;

// interleaved scan input: [tok][h][f][64], f: 0=r, 1=k, 2=wd, 3=v  (256MB)
__device__ float g_seq[(size_t)NT*32*4*64];

// ---------------- packed f32x2 helpers ----------------
__device__ __forceinline__ ull pk(float lo, float hi){
    ull r; asm("mov.b64 %0,{%1,%2};" : "=l"(r) : "f"(lo), "f"(hi)); return r;
}
__device__ __forceinline__ ull dup(float x){
    ull r; asm("mov.b64 %0,{%1,%1};" : "=l"(r) : "f"(x)); return r;
}
__device__ __forceinline__ float2 up2(ull a){
    float2 f; asm("mov.b64 {%0,%1},%2;" : "=f"(f.x), "=f"(f.y) : "l"(a)); return f;
}
__device__ __forceinline__ ull fma2(ull a, ull b, ull c){
    ull d; asm("fma.rn.f32x2 %0,%1,%2,%3;" : "=l"(d) : "l"(a), "l"(b), "l"(c)); return d;
}
__device__ __forceinline__ ull mul2(ull a, ull b){
    ull d; asm("mul.rn.f32x2 %0,%1,%2;" : "=l"(d) : "l"(a), "l"(b)); return d;
}
__device__ __forceinline__ void cpa16(uint32_t dst, const void* src){
    asm volatile("cp.async.cg.shared.global [%0],[%1],16;\n" :: "r"(dst), "l"(src) : "memory");
}
__device__ __forceinline__ void cpa_commit(){
    asm volatile("cp.async.commit_group;\n" ::: "memory");
}
__device__ __forceinline__ void cpa_wait0(){
    asm volatile("cp.async.wait_group 0;\n" ::: "memory");
}
__device__ __forceinline__ uint32_t tf32r(float f){
    uint32_t u; asm("cvt.rna.tf32.f32 %0, %1;" : "=r"(u) : "f"(f)); return u;
}
__device__ __forceinline__ void mma_tf32(float* c, uint32_t a0, uint32_t a1,
                                         uint32_t a2, uint32_t a3,
                                         uint32_t b0, uint32_t b1){
    asm("mma.sync.aligned.m16n8k8.row.col.f32.tf32.tf32.f32 "
        "{%0,%1,%2,%3}, {%4,%5,%6,%7}, {%8,%9}, {%0,%1,%2,%3};"
        : "+f"(c[0]), "+f"(c[1]), "+f"(c[2]), "+f"(c[3])
        : "r"(a0), "r"(a1), "r"(a2), "r"(a3), "r"(b0), "r"(b1));
}

// ---------------- k_fused shared layout (float offsets) ----------------
#define OFF_XXX 0            // [64][132]  tf32 bits   8448
#define OFF_W2  8448         // [128][136]            17408 -> 25856
#define OFF_DW1 25856        // 2 x [128][68]         17408 -> 43264
#define OFF_XW  43264        // [64][132]              8448 -> 51712
// Phase A scratch overlays the XW region (XW not live in phase A):
#define OFF_A   43264        // [32][72]   2304 -> 45568
#define OFF_BT  45568        // [128][36]  4608 -> 50176
// phase C reuse: D1 at 0 ([64][68]), DW2 at OFF_W2 ([64][128])
#define SMEM_F 51712
#define SMEM_BYTES (SMEM_F*4)

// =====================================================================
// k_fused: token-shift mix + decay LoRA. 64 tokens/block, 256 threads,
// grid 128. Phases A and B use tf32 mma.sync; d1-accum / Phase C fp32.
// =====================================================================
__global__ __launch_bounds__(256, 1) void k_fused(
    const float* __restrict__ hidden, const float* __restrict__ attn_x,
    const float* __restrict__ maa_x,  const float* __restrict__ maa_w,
    const float* __restrict__ maa_k,  const float* __restrict__ maa_v,
    const float* __restrict__ maa_r,  const float* __restrict__ w1,
    const float* __restrict__ w2,     const float* __restrict__ dw1,
    const float* __restrict__ dw2,    const float* __restrict__ tdecay)
{
    extern __shared__ float sm[];
    const int tid = threadIdx.x;
    const int tx = tid & 15, ty = tid >> 4;
    const int bt0 = blockIdx.x * 64;

    const uint32_t smb = (uint32_t)__cvta_generic_to_shared(sm);

    // mma thread geometry (phases A and B)
    const int wid  = tid >> 5, lane = tid & 31;
    const int gid  = lane >> 2, tig = lane & 3;
    const int tokb = (wid & 3) * 16;      // token tile base (0..48)
    const int nh   = wid >> 2;            // n half (0..1)

    // stage w2 (stride 136) + dw1 chunk via cp.async (one commit group)
    auto stage_wd = [&](int c0, int buf){
        #pragma unroll
        for (int l = 0; l < 16; l++){
            int i = tid + l*256;                // 0..4095 float4s
            int row = i >> 5, c4 = i & 31;
            cpa16(smb + (uint32_t)(OFF_W2 + row*136 + c4*4)*4u,
                  w2 + (size_t)row*CC + c0 + c4*4);
        }
        #pragma unroll
        for (int l = 0; l < 8; l++){
            int i = tid + l*256;                // 0..2047 float4s
            int row = i >> 4, c4 = i & 15;
            cpa16(smb + (uint32_t)(OFF_DW1 + buf*8704 + row*68 + c4*4)*4u,
                  dw1 + (size_t)(c0 + row)*64 + c4*4);
        }
        cpa_commit();
    };

    stage_wd(0, 0);

    // ========== Phase A: xxx = tanh(z @ W1[:,:128]) via tf32 mma ==========
    {
        float* As  = sm + OFF_A;    // [32][72] tf32 bits (k-major)
        float* Bst = sm + OFF_BT;   // [128][36] tf32 bits (n-major)
        float rx[8], rp[8], rm[8], rb[16];

        auto prefA = [&](int kc){
            #pragma unroll
            for (int l = 0; l < 8; l++){
                int i = tid + l*256; int kk = i & 31, tl = i >> 5;
                int tok = bt0 + tl; int c = kc + kk;
                rx[l] = hidden[(size_t)tok*CC + c];
                rp[l] = ((tok & (TT-1)) == 0) ? attn_x[(size_t)(tok >> 12)*CC + c]
                                              : hidden[(size_t)(tok-1)*CC + c];
                rm[l] = maa_x[c];
            }
            #pragma unroll
            for (int l = 0; l < 16; l++){
                int i = tid + l*256; int kk = i >> 7, n = i & 127;
                rb[l] = w1[(size_t)(kc+kk)*160 + n];
            }
        };

        float cA[8][4];
        #pragma unroll
        for (int ns = 0; ns < 8; ns++)
            #pragma unroll
            for (int j = 0; j < 4; j++) cA[ns][j] = 0.f;

        prefA(0);
        for (int kc = 0; kc < CC; kc += 32){
            #pragma unroll
            for (int l = 0; l < 8; l++){
                int i = tid + l*256; int kk = i & 31, tl = i >> 5;
                float z = rx[l] + (rp[l] - rx[l])*rm[l];
                As[kk*72 + tl] = __uint_as_float(tf32r(z));
            }
            #pragma unroll
            for (int l = 0; l < 16; l++){
                int i = tid + l*256; int kk = i >> 7, n = i & 127;
                Bst[n*36 + kk] = __uint_as_float(tf32r(rb[l]));
            }
            __syncthreads();
            if (kc + 32 < CC) prefA(kc + 32);
            #pragma unroll
            for (int ks = 0; ks < 4; ks++){
                const int k0 = ks*8;
                uint32_t a0 = __float_as_uint(As[(k0+tig  )*72 + tokb + gid    ]);
                uint32_t a1 = __float_as_uint(As[(k0+tig  )*72 + tokb + gid + 8]);
                uint32_t a2 = __float_as_uint(As[(k0+tig+4)*72 + tokb + gid    ]);
                uint32_t a3 = __float_as_uint(As[(k0+tig+4)*72 + tokb + gid + 8]);
                #pragma unroll
                for (int ns = 0; ns < 8; ns++){
                    const int n0 = nh*64 + ns*8;
                    uint32_t b0 = __float_as_uint(Bst[(n0+gid)*36 + k0 + tig    ]);
                    uint32_t b1 = __float_as_uint(Bst[(n0+gid)*36 + k0 + tig + 4]);
                    mma_tf32(cA[ns], a0, a1, a2, a3, b0, b1);
                }
            }
            __syncthreads();
        }
        // epilogue: tanh -> xxx_s tf32 bits, stride 132
        #pragma unroll
        for (int ns = 0; ns < 8; ns++){
            const int n0 = nh*64 + ns*8 + 2*tig;
            const int t0 = tokb + gid;
            sm[OFF_XXX + (t0    )*132 + n0    ] = __uint_as_float(tf32r(tanhf(cA[ns][0])));
            sm[OFF_XXX + (t0    )*132 + n0 + 1] = __uint_as_float(tf32r(tanhf(cA[ns][1])));
            sm[OFF_XXX + (t0 + 8)*132 + n0    ] = __uint_as_float(tf32r(tanhf(cA[ns][2])));
            sm[OFF_XXX + (t0 + 8)*132 + n0 + 1] = __uint_as_float(tf32r(tanhf(cA[ns][3])));
        }
    }

    // ================= Phase B (tf32 mma) =================
    float* xxx_s = sm + OFF_XXX;   // tf32 bits, stride 132
    float* w2_s  = sm + OFF_W2;    // stride 136
    float* xw_s  = sm + OFF_XW;    // stride 132

    ull acc_d1[4][2];
    #pragma unroll
    for (int i = 0; i < 4; i++){ acc_d1[i][0] = 0ull; acc_d1[i][1] = 0ull; }

    for (int c0 = 0; c0 < CC; c0 += 128){
        const int cbuf = (c0 >> 7) & 1;
        cpa_wait0();
        __syncthreads();           // w2/dw1 ready; also covers xxx after phase A

        const int ncol0 = nh*64 + 2*tig;     // + ns*8 per tile
        const int tok0  = bt0 + tokb + gid;  // rows tok0, tok0+8

        // x / diff operands in fragment layout
        float xf[2][8][2], df[2][8][2];
        #pragma unroll
        for (int rr = 0; rr < 2; rr++){
            const int tok = tok0 + rr*8;
            const size_t gbase = (size_t)tok*CC + c0 + ncol0;
            const float* prow = ((tok & (TT-1)) == 0) ? (attn_x + (size_t)(tok >> 12)*CC)
                                                      : (hidden + (size_t)(tok-1)*CC);
            #pragma unroll
            for (int ns = 0; ns < 8; ns++){
                float2 xv = *(const float2*)&hidden[gbase + ns*8];
                float2 pv = *(const float2*)&prow[c0 + ncol0 + ns*8];
                xf[rr][ns][0] = xv.x;        xf[rr][ns][1] = xv.y;
                df[rr][ns][0] = pv.x - xv.x; df[rr][ns][1] = pv.y - xv.y;
            }
        }

        #pragma unroll
        for (int f = 0; f < 4; f++){
            float cB[8][4];
            #pragma unroll
            for (int ns = 0; ns < 8; ns++)
                #pragma unroll
                for (int j = 0; j < 4; j++) cB[ns][j] = 0.f;

            #pragma unroll
            for (int ks = 0; ks < 4; ks++){
                const int k0 = f*32 + ks*8;
                uint32_t a0 = __float_as_uint(xxx_s[(tokb+gid  )*132 + k0 + tig    ]);
                uint32_t a1 = __float_as_uint(xxx_s[(tokb+gid+8)*132 + k0 + tig    ]);
                uint32_t a2 = __float_as_uint(xxx_s[(tokb+gid  )*132 + k0 + tig + 4]);
                uint32_t a3 = __float_as_uint(xxx_s[(tokb+gid+8)*132 + k0 + tig + 4]);
                #pragma unroll
                for (int ns = 0; ns < 8; ns++){
                    const int nn = nh*64 + ns*8 + gid;
                    uint32_t b0 = tf32r(w2_s[(k0+tig  )*136 + nn]);
                    uint32_t b1 = tf32r(w2_s[(k0+tig+4)*136 + nn]);
                    mma_tf32(cB[ns], a0, a1, a2, a3, b0, b1);
                }
            }
            // epilogue for this f (fragment layout)
            const float* maaf = (f==0) ? maa_w : (f==1) ? maa_k : (f==2) ? maa_v : maa_r;
            const int slot = (f==1) ? 1 : (f==2) ? 3 : 0;
            #pragma unroll
            for (int ns = 0; ns < 8; ns++){
                const int col = c0 + ncol0 + ns*8;
                float2 mv = *(const float2*)&maaf[col];
                #pragma unroll
                for (int rr = 0; rr < 2; rr++){
                    float o0 = xf[rr][ns][0] + df[rr][ns][0]*(mv.x + cB[ns][rr*2    ]);
                    float o1 = xf[rr][ns][1] + df[rr][ns][1]*(mv.y + cB[ns][rr*2 + 1]);
                    if (f == 0){
                        *(float2*)&xw_s[(tokb+gid+rr*8)*132 + ncol0 + ns*8] = make_float2(o0, o1);
                    } else {
                        const int tok = tok0 + rr*8;
                        const int hh = col >> 6, lmm = col & 63;
                        *(float2*)&g_seq[((size_t)tok*32 + hh)*256 + slot*64 + lmm] =
                            make_float2(o0, o1);
                    }
                }
            }
        }
        __syncthreads();           // xw_s complete; w2/dw1 fully consumed

        if (c0 + 128 < CC) stage_wd(c0 + 128, cbuf ^ 1);
        else               cpa_commit();

        const float* dw1c = sm + OFF_DW1 + cbuf*8704;
        #pragma unroll 2
        for (int kk = 0; kk < 128; kk++){
            ulonglong2 bp = *(const ulonglong2*)&dw1c[kk*68 + tx*4];
            #pragma unroll
            for (int i = 0; i < 4; i++){
                ull ad = dup(xw_s[(ty*4 + i)*132 + kk]);
                acc_d1[i][0] = fma2(ad, bp.x, acc_d1[i][0]);
                acc_d1[i][1] = fma2(ad, bp.y, acc_d1[i][1]);
            }
        }
    }
    cpa_wait0();
    __syncthreads();

    // ================= Phase C: wd = exp(-exp(td + tanh(d1) @ dw2)) =================
    float* d1_s  = sm;                 // [64][68]
    float* dw2_s = sm + OFF_W2;        // [64][128]
    #pragma unroll
    for (int i = 0; i < 4; i++){
        float2 e0 = up2(acc_d1[i][0]);
        float2 e1 = up2(acc_d1[i][1]);
        int r = (ty*4 + i)*68 + tx*4;
        d1_s[r]   = tanhf(e0.x);
        d1_s[r+1] = tanhf(e0.y);
        d1_s[r+2] = tanhf(e1.x);
        d1_s[r+3] = tanhf(e1.y);
    }
    __syncthreads();

    for (int c0 = 0; c0 < CC; c0 += 128){
        #pragma unroll
        for (int l = 0; l < 32; l++){
            int i = tid + l*256;
            dw2_s[i] = dw2[(size_t)(i >> 7)*CC + c0 + (i & 127)];
        }
        __syncthreads();
        ull wacc[4][4];
        #pragma unroll
        for (int i = 0; i < 4; i++)
            #pragma unroll
            for (int j = 0; j < 4; j++) wacc[i][j] = 0ull;
        #pragma unroll 4
        for (int jj = 0; jj < 64; jj++){
            ulonglong2 wa = *(const ulonglong2*)&dw2_s[jj*128 + tx*8];
            ulonglong2 wb = *(const ulonglong2*)&dw2_s[jj*128 + tx*8 + 4];
            #pragma unroll
            for (int i = 0; i < 4; i++){
                ull ad = dup(d1_s[(ty*4 + i)*68 + jj]);
                wacc[i][0] = fma2(ad, wa.x, wacc[i][0]);
                wacc[i][1] = fma2(ad, wa.y, wacc[i][1]);
                wacc[i][2] = fma2(ad, wb.x, wacc[i][2]);
                wacc[i][3] = fma2(ad, wb.y, wacc[i][3]);
            }
        }
        const int cb = c0 + tx*8;
        const int hh = cb >> 6, lmm = cb & 63;
        float4 t0 = *(const float4*)&tdecay[cb];
        float4 t1 = *(const float4*)&tdecay[cb + 4];
        float td[8] = {t0.x,t0.y,t0.z,t0.w,t1.x,t1.y,t1.z,t1.w};
        #pragma unroll
        for (int i = 0; i < 4; i++){
            const int tl = ty*4 + i;
            float mq[8];
            #pragma unroll
            for (int jp = 0; jp < 4; jp++){
                float2 q = up2(wacc[i][jp]);
                mq[2*jp] = q.x; mq[2*jp+1] = q.y;
            }
            float o[8];
            #pragma unroll
            for (int e = 0; e < 8; e++) o[e] = expf(-expf(td[e] + mq[e]));
            float* dst = &g_seq[((size_t)(bt0 + tl)*32 + hh)*256 + 128 + lmm];
            *(float4*)&dst[0] = make_float4(o[0],o[1],o[2],o[3]);
            *(float4*)&dst[4] = make_float4(o[4],o[5],o[6],o[7]);
        }
        __syncthreads();
    }
}

// =====================================================================
// k_scan: exact R4 version (measured 365us). 128 blocks = (b, h, m-half).
// =====================================================================
__global__ __launch_bounds__(256) void k_scan(
    const float* __restrict__ attn_kv, const float* __restrict__ faaaa,
    float* __restrict__ out)
{
    __shared__ float ring[32*256];
    __shared__ float partial[8][264];

    const int tid = threadIdx.x;
    const int bid = blockIdx.x;
    const int b = bid >> 6, h = (bid >> 1) & 31, half = bid & 1;
    const int lm = tid & 31, q = tid >> 5;
    const int mg = half*32 + lm;

    const ull ud = dup(faaaa[h]);

    ull s2[4];
    const float* kvp = attn_kv + ((size_t)(b*32 + h))*4096;
    #pragma unroll
    for (int j = 0; j < 4; j++){
        int n0 = q*8 + 2*j;
        s2[j] = pk(kvp[n0*64 + mg], kvp[(n0+1)*64 + mg]);
    }

    const float4* srcb = (const float4*)g_seq + ((size_t)b*TT)*2048 + h*64;
    const uint32_t rbase = (uint32_t)__cvta_generic_to_shared(ring);
    const int e0 = tid*2, e1 = tid*2 + 1;
    const int s0 = e0 >> 6, o0 = e0 & 63;
    const int s1 = e1 >> 6, o1 = e1 & 63;

    #pragma unroll
    for (int gg = 0; gg < 3; gg++){
        int t0 = gg*8;
        int ta = t0 + s0, tb = t0 + s1;
        cpa16(rbase + (uint32_t)((ta & 31)*1024 + o0*16), srcb + (size_t)ta*2048 + o0);
        cpa16(rbase + (uint32_t)((tb & 31)*1024 + o1*16), srcb + (size_t)tb*2048 + o1);
        cpa_commit();
    }

    const size_t obase = (size_t)b*TT*CC + h*64 + half*32;
    const int nb = q*8;

    for (int g = 0; g < TT/8; g++){
        asm volatile("cp.async.wait_group 2;\n" ::: "memory");
        __syncthreads();
        #pragma unroll
        for (int ti = 0; ti < 8; ti++){
            const float* st = &ring[(((g << 3) + ti) & 31) << 8];
            const ull vd = dup(st[192 + mg]);
            ulonglong2 ra = *(const ulonglong2*)&st[nb];
            ulonglong2 rb = *(const ulonglong2*)&st[nb + 4];
            ulonglong2 ka = *(const ulonglong2*)&st[64 + nb];
            ulonglong2 kb = *(const ulonglong2*)&st[64 + nb + 4];
            ulonglong2 wa = *(const ulonglong2*)&st[128 + nb];
            ulonglong2 wb = *(const ulonglong2*)&st[128 + nb + 4];
            ull r2[4]  = {ra.x, ra.y, rb.x, rb.y};
            ull k2[4]  = {ka.x, ka.y, kb.x, kb.y};
            ull w2v[4] = {wa.x, wa.y, wb.x, wb.y};
            ull y0 = 0ull, y1 = 0ull;
            #pragma unroll
            for (int j = 0; j < 4; j++){
                ull a2 = mul2(k2[j], vd);
                ull t2 = fma2(ud, a2, s2[j]);
                if (j & 1) y1 = fma2(r2[j], t2, y1);
                else       y0 = fma2(r2[j], t2, y0);
                s2[j] = fma2(w2v[j], s2[j], a2);
            }
            float2 f0 = up2(y0), f1 = up2(y1);
            partial[ti][q*33 + lm] = (f0.x + f0.y) + (f1.x + f1.y);
        }
        __syncthreads();
        {
            const int s = tid >> 5;
            float y = 0.f;
            #pragma unroll
            for (int q2 = 0; q2 < 8; q2++) y += partial[s][q2*33 + lm];
            out[obase + (size_t)((g << 3) + s)*CC + lm] = y;
        }
        if (g + 3 < TT/8){
            int t0 = (g + 3)*8;
            int ta = t0 + s0, tb = t0 + s1;
            cpa16(rbase + (uint32_t)((ta & 31)*1024 + o0*16), srcb + (size_t)ta*2048 + o0);
            cpa16(rbase + (uint32_t)((tb & 31)*1024 + o1*16), srcb + (size_t)tb*2048 + o1);
        }
        cpa_commit();
    }
}

// =====================================================================
extern "C" void kernel_launch(void* const* d_in, const int* in_sizes, int n_in,
                              void* d_out, int out_size) {
    const float* hidden  = (const float*)d_in[0];
    const float* attn_x  = (const float*)d_in[1];
    const float* attn_kv = (const float*)d_in[2];
    const float* maa_x   = (const float*)d_in[4];
    const float* maa_w   = (const float*)d_in[5];
    const float* maa_k   = (const float*)d_in[6];
    const float* maa_v   = (const float*)d_in[7];
    const float* maa_r   = (const float*)d_in[8];
    const float* w1      = (const float*)d_in[10];
    const float* w2      = (const float*)d_in[11];
    const float* tdecay  = (const float*)d_in[12];
    const float* dw1     = (const float*)d_in[13];
    const float* dw2     = (const float*)d_in[14];
    const float* faaaa   = (const float*)d_in[15];
    float* out = (float*)d_out;

    static bool attr_set = false;
    if (!attr_set){
        cudaFuncSetAttribute(k_fused, cudaFuncAttributeMaxDynamicSharedMemorySize, SMEM_BYTES);
        attr_set = true;
    }

    k_fused<<<NT/64, 256, SMEM_BYTES>>>(hidden, attn_x, maa_x, maa_w, maa_k,
                                        maa_v, maa_r, w1, w2, dw1, dw2, tdecay);
    k_scan <<<128, 256>>>(attn_kv, faaaa, out);
}